// round 8
// baseline (speedup 1.0000x reference)
#include <cuda_runtime.h>
#include <math.h>

#define NANCH   8400
#define MAXB    32
#define NCLS    80
#define MAXDET  100
#define NBKT    1024
#define CCAP    256      // chunk capacity (= NMS sort width = blockDim)
#define CAPSEL  280      // preselect target (>= max candidates greedy consumes)
#define LISTCAP 1024     // per-image candidate list capacity

// ---------------- device scratch (static zero-init; self-cleaning across graph replays) ----------------
__device__ float              g_scores[MAXB * NANCH];
__device__ float4             g_boxes [MAXB * NANCH];
__device__ int                g_labels[MAXB * NANCH];
__device__ int                g_maxabs[MAXB];           // float bits (non-negative), atomicMax
__device__ int                g_hist  [MAXB][NBKT];     // per-image score histogram
__device__ unsigned long long g_cand  [MAXB][LISTCAP];  // preselected (key) list
__device__ int                g_ccnt  [MAXB];           // list counters

__device__ __forceinline__ float sigmoidf_(float x) {
    return 1.0f / (1.0f + expf(-x));
}

__device__ __forceinline__ int score_bucket(float scv) {
    int bkt = (int)(scv * 1024.0f);
    return bkt > NBKT - 1 ? NBKT - 1 : bkt;
}

__device__ __forceinline__ unsigned long long make_key(float scv, unsigned idx) {
    unsigned u = __float_as_uint(scv);
    u = ~(u ^ 0x80000000u);                 // positive-float descending, idx ascending
    return ((unsigned long long)u << 32) | idx;
}

__device__ __forceinline__ float key_score(unsigned long long k) {
    unsigned u = (unsigned)(k >> 32);
    return __uint_as_float((~u) ^ 0x80000000u);
}

// Tcut: lowest bucket such that count(bucket >= Tcut) >= CAPSEL (0 if total < CAPSEL).
__device__ int compute_tcut(const int* hist, int lane) {
    int base = 1023 - 32 * lane;            // lane covers buckets [base-31, base]
    int s = 0;
    #pragma unroll 8
    for (int k = 0; k < 32; ++k) s += hist[base - k];
    int cum = s;
    #pragma unroll
    for (int o = 1; o < 32; o <<= 1) {
        int v = __shfl_up_sync(0xFFFFFFFFu, cum, o);
        if (lane >= o) cum += v;
    }
    int tcut = 0;
    unsigned ball = __ballot_sync(0xFFFFFFFFu, cum >= CAPSEL);
    if (ball) {
        int l0 = __ffs(ball) - 1;
        if (lane == l0) {
            int run = cum - s;
            int k = 0;
            for (; k < 32; ++k) {
                run += hist[base - k];
                if (run >= CAPSEL) break;
            }
            tcut = base - k;
        }
        tcut = __shfl_sync(0xFFFFFFFFu, tcut, l0);
    }
    return tcut;
}

// ---------------- decode: 2 anchors/thread (float2), smem histogram, boxmax ----------------
__global__ void __launch_bounds__(256) k_decode(
    const float* __restrict__ cls0, const float* __restrict__ reg0, const float* __restrict__ obj0,
    const float* __restrict__ cls1, const float* __restrict__ reg1, const float* __restrict__ obj1,
    const float* __restrict__ cls2, const float* __restrict__ reg2, const float* __restrict__ obj2)
{
    __shared__ int s_h[NBKT];
    const int b   = blockIdx.y;
    const int tid = threadIdx.x;
    const int a   = (blockIdx.x * blockDim.x + tid) * 2;
    float m4 = 0.0f;

    ((int4*)s_h)[tid] = make_int4(0, 0, 0, 0);
    __syncthreads();

    if (a < NANCH) {
        const float *cls, *reg, *obj;
        int a0, w, hw; float s;
        if (a < 6400)      { cls = cls0; reg = reg0; obj = obj0; a0 = a;        w = 80; hw = 6400; s = 8.0f;  }
        else if (a < 8000) { cls = cls1; reg = reg1; obj = obj1; a0 = a - 6400; w = 40; hw = 1600; s = 16.0f; }
        else               { cls = cls2; reg = reg2; obj = obj2; a0 = a - 8000; w = 20; hw = 400;  s = 32.0f; }

        const int hw2 = hw >> 1;
        const int q   = a0 >> 1;

        const float2* c2 = (const float2*)(cls + (size_t)b * NCLS * hw) + q;
        float2 v = c2[0];
        float m0 = v.x, m1 = v.y;
        int   l0 = 0,   l1 = 0;
        #pragma unroll 8
        for (int c = 1; c < NCLS; ++c) {
            v = c2[(size_t)c * hw2];
            if (v.x > m0) { m0 = v.x; l0 = c; }
            if (v.y > m1) { m1 = v.y; l1 = c; }
        }

        float2 ov = *((const float2*)(obj + (size_t)b * hw) + q);
        const float* rb = reg + (size_t)b * 4 * hw;
        float2 r0 = *((const float2*)(rb)          + q);
        float2 r1 = *((const float2*)(rb +     hw) + q);
        float2 r2 = *((const float2*)(rb + 2 * hw) + q);
        float2 r3 = *((const float2*)(rb + 3 * hw) + q);

        float mm[2] = { m0, m1 };
        int   ll[2] = { l0, l1 };
        float oo[2] = { ov.x, ov.y };
        float rx[2] = { r0.x, r0.y };
        float ry[2] = { r1.x, r1.y };
        float rw[2] = { r2.x, r2.y };
        float rh[2] = { r3.x, r3.y };

        const size_t base = (size_t)b * NANCH + a;
        float sc[2];
        #pragma unroll
        for (int i = 0; i < 2; ++i) {
            sc[i] = __fmul_rn(sigmoidf_(mm[i]), sigmoidf_(oo[i]));
            int ai = a0 + i;
            float px = (float)(ai % w) * s;
            float py = (float)(ai / w) * s;
            float cx = __fadd_rn(__fmul_rn(rx[i], s), px);
            float cy = __fadd_rn(__fmul_rn(ry[i], s), py);
            float bw = __fmul_rn(expf(rw[i]), s);
            float bh = __fmul_rn(expf(rh[i]), s);
            float hx = __fmul_rn(bw, 0.5f);
            float hy = __fmul_rn(bh, 0.5f);
            float x1 = __fsub_rn(cx, hx), y1 = __fsub_rn(cy, hy);
            float x2 = __fadd_rn(cx, hx), y2 = __fadd_rn(cy, hy);
            g_boxes[base + i] = make_float4(x1, y1, x2, y2);
            m4 = fmaxf(m4, fmaxf(fmaxf(fabsf(x1), fabsf(y1)), fmaxf(fabsf(x2), fabsf(y2))));
            if (sc[i] >= 0.01f)
                atomicAdd(&s_h[score_bucket(sc[i])], 1);
        }
        *((float2*)(g_scores + base)) = make_float2(sc[0], sc[1]);
        *((int2*)(g_labels + base))   = make_int2(ll[0], ll[1]);
    }

    #pragma unroll
    for (int o = 16; o > 0; o >>= 1)
        m4 = fmaxf(m4, __shfl_xor_sync(0xFFFFFFFFu, m4, o));
    if ((threadIdx.x & 31) == 0 && m4 > 0.0f)
        atomicMax(&g_maxabs[b], __float_as_int(m4));

    __syncthreads();
    #pragma unroll
    for (int k = tid; k < NBKT; k += 256) {
        int hv = s_h[k];
        if (hv) atomicAdd(&g_hist[b][k], hv);
    }
}

// ---------------- select: compact top-(>=CAPSEL) candidates into per-image list ----------------
__global__ void __launch_bounds__(256) k_select()
{
    __shared__ int s_h[NBKT];
    __shared__ int s_tcut;
    const int b   = blockIdx.y;
    const int tid = threadIdx.x;

    ((int4*)s_h)[tid] = ((const int4*)&g_hist[b][0])[tid];
    __syncthreads();
    if (tid < 32) {
        int t = compute_tcut(s_h, tid);
        if (tid == 0) s_tcut = t;
    }
    __syncthreads();
    const int tcut = s_tcut;

    const int i4 = blockIdx.x * 256 + tid;
    if (i4 < NANCH / 4) {
        float4 s4 = *((const float4*)(g_scores + (size_t)b * NANCH) + i4);
        float sv[4] = { s4.x, s4.y, s4.z, s4.w };
        #pragma unroll
        for (int k = 0; k < 4; ++k) {
            float scv = sv[k];
            if (scv >= 0.01f && score_bucket(scv) >= tcut) {
                int slot = atomicAdd(&g_ccnt[b], 1);
                if (slot < LISTCAP)
                    g_cand[b][slot] = make_key(scv, (unsigned)(i4 * 4 + k));
            }
        }
    }
}

__device__ __forceinline__ unsigned long long shflx64(unsigned long long v, int j) {
    return __shfl_xor_sync(0xFFFFFFFFu, v, j);
}

// exact reference IoU>thr test on offset boxes
__device__ __forceinline__ bool iou_gt(float4 a, float4 bx) {
    float tlx = fmaxf(a.x, bx.x), tly = fmaxf(a.y, bx.y);
    float brx = fminf(a.z, bx.z), bry = fminf(a.w, bx.w);
    float ww = fmaxf(__fsub_rn(brx, tlx), 0.0f);
    float hh = fmaxf(__fsub_rn(bry, tly), 0.0f);
    float inter = __fmul_rn(ww, hh);
    float a1 = __fmul_rn(__fsub_rn(a.z, a.x), __fsub_rn(a.w, a.y));
    float a2 = __fmul_rn(__fsub_rn(bx.z, bx.x), __fsub_rn(bx.w, bx.y));
    float den = __fadd_rn(__fsub_rn(__fadd_rn(a1, a2), inter), 1e-6f);
    return __fdiv_rn(inter, den) > 0.65f;
}

// ---------------- NMS ----------------
__global__ void __launch_bounds__(256) k_nms(float* __restrict__ out, int B)
{
    __shared__ __align__(16) int                s_hist[NBKT];
    __shared__ __align__(16) unsigned long long s_key[CCAP];
    __shared__ __align__(16) float4             s_box[CCAP];
    __shared__ __align__(16) unsigned           s_row[CCAP][8];
    __shared__ __align__(16) unsigned char      s_lab8[CCAP];
    __shared__ __align__(16) unsigned char      s_flags[CCAP];
    __shared__ __align__(16) unsigned char      s_kord[CCAP];
    __shared__ float4             s_keptb[MAXDET];
    __shared__ unsigned char      s_klab[MAXDET];
    __shared__ int                s_kepti[MAXDET];
    __shared__ float              s_off;
    __shared__ int                s_cnt, s_kc, s_lo, s_hi, s_ptr, s_tcut, s_ccnt;

    const int b   = blockIdx.x;
    const int tid = threadIdx.x;
    const size_t base = (size_t)b * NANCH;

    if (tid == 0) {
        s_off = __fadd_rn(__int_as_float(g_maxabs[b]), 1.0f);
        g_maxabs[b] = 0;
        s_ptr = -1;
        s_kc = 0;
        s_ccnt = g_ccnt[b];
        g_ccnt[b] = 0;
    }
    int4 h4;
    {
        int4* gh4 = (int4*)&g_hist[b][0];
        h4 = gh4[tid];
        ((int4*)s_hist)[tid] = h4;
        gh4[tid] = make_int4(0, 0, 0, 0);
    }
    __syncthreads();
    {
        int maxk = -1;
        if (h4.w) maxk = tid * 4 + 3;
        else if (h4.z) maxk = tid * 4 + 2;
        else if (h4.y) maxk = tid * 4 + 1;
        else if (h4.x) maxk = tid * 4;
        #pragma unroll
        for (int o = 16; o > 0; o >>= 1)
            maxk = max(maxk, __shfl_xor_sync(0xFFFFFFFFu, maxk, o));
        if ((tid & 31) == 0) atomicMax(&s_ptr, maxk);
        if (tid < 32) {
            int t = compute_tcut(s_hist, tid);
            if (tid == 0) s_tcut = t;
        }
    }
    __syncthreads();
    const float off = s_off;
    const int   tcut = s_tcut;
    const int   ccnt = s_ccnt;
    const bool  list_ok = (ccnt <= LISTCAP);

    for (;;) {
        if (s_kc >= MAXDET || s_ptr < 0) break;

        if (tid == 0) {
            int acc = 0;
            int hi = s_ptr, p = hi;
            while (p >= 0) {
                int h = s_hist[p];
                if (acc > 0 && acc + h > CCAP) break;
                acc += h; --p;
                if (acc >= CCAP) break;
            }
            s_lo = p + 1; s_hi = hi; s_ptr = p; s_cnt = 0;
        }
        __syncthreads();
        const int lo = s_lo, hi = s_hi;

        // ---- compact: list mode (tiny) if chunk fully above Tcut, else full sweep (exact fallback) ----
        if (list_ok && lo >= tcut) {
            for (int t = tid; t < ccnt; t += 256) {
                unsigned long long key = g_cand[b][t];
                int bkt = score_bucket(key_score(key));
                if (bkt >= lo && bkt <= hi) {
                    int p = atomicAdd(&s_cnt, 1);
                    if (p < CCAP) s_key[p] = key;
                }
            }
        } else {
            for (int i4 = tid; i4 < NANCH / 4; i4 += 256) {
                float4 s4 = *((const float4*)(g_scores + base) + i4);
                float sv[4] = { s4.x, s4.y, s4.z, s4.w };
                #pragma unroll
                for (int k = 0; k < 4; ++k) {
                    float scv = sv[k];
                    if (scv >= 0.01f) {
                        int bkt = score_bucket(scv);
                        if (bkt >= lo && bkt <= hi) {
                            int p = atomicAdd(&s_cnt, 1);
                            if (p < CCAP) s_key[p] = make_key(scv, (unsigned)(i4 * 4 + k));
                        }
                    }
                }
            }
        }
        __syncthreads();
        int cN = s_cnt; if (cN > CCAP) cN = CCAP;
        if (tid >= cN) s_key[tid] = 0xFFFFFFFFFFFFFFFFull;

        // ---- bitonic sort 256 keys ascending (= score desc, idx asc) ----
        {
            unsigned long long v = s_key[tid];
            #pragma unroll
            for (int k = 2; k <= 32; k <<= 1) {
                bool up = ((tid & k) == 0);
                #pragma unroll
                for (int j = k >> 1; j > 0; j >>= 1) {
                    unsigned long long p = shflx64(v, j);
                    bool keepSmall = (((tid & j) == 0) == up);
                    if (keepSmall ? (p < v) : (p > v)) v = p;
                }
            }
            s_key[tid] = v;
            __syncthreads();
        }
        #pragma unroll
        for (int k = 64; k <= CCAP; k <<= 1) {
            for (int j = k >> 1; j >= 32; j >>= 1) {
                int i = tid, l = i ^ j;
                if (l > i) {
                    unsigned long long A = s_key[i], Bv = s_key[l];
                    bool up = ((i & k) == 0);
                    if ((A > Bv) == up) { s_key[i] = Bv; s_key[l] = A; }
                }
                __syncthreads();
            }
            {
                unsigned long long v = s_key[tid];
                bool up = ((tid & k) == 0);
                #pragma unroll
                for (int j = 16; j > 0; j >>= 1) {
                    unsigned long long p = shflx64(v, j);
                    bool keepSmall = (((tid & j) == 0) == up);
                    if (keepSmall ? (p < v) : (p > v)) v = p;
                }
                s_key[tid] = v;
                __syncthreads();
            }
        }

        // ---- gather shifted boxes + labels; predead vs previously-kept; zero rows ----
        const int kc0 = s_kc;
        float4 mybox = make_float4(0.f, 0.f, 0.f, 0.f);
        int    mylab = -1;
        int    pred  = 1;
        if (tid < cN) {
            int idx = (int)(s_key[tid] & 0xFFFFFFFFull);
            mybox = g_boxes[base + idx];
            mylab = g_labels[base + idx];
            float t = __fmul_rn((float)mylab, off);
            mybox.x = __fadd_rn(mybox.x, t);
            mybox.y = __fadd_rn(mybox.y, t);
            mybox.z = __fadd_rn(mybox.z, t);
            mybox.w = __fadd_rn(mybox.w, t);
            s_box[tid]  = mybox;
            s_lab8[tid] = (unsigned char)mylab;
            pred = 0;
            for (int j2 = 0; j2 < kc0; ++j2)
                if (s_klab[j2] == (unsigned char)mylab && iou_gt(s_keptb[j2], mybox)) { pred = 1; break; }
        }
        {
            uint4 z = make_uint4(0u, 0u, 0u, 0u);
            ((uint4*)&s_row[tid][0])[0] = z;
            ((uint4*)&s_row[tid][0])[1] = z;
        }
        __syncthreads();

        // ---- sparse rows: 16-labels-per-load vcmpeq scan, IoU only on same-label hits ----
        {
            unsigned any = 0;
            if (tid < cN && pred == 0) {
                const uint4* lab16 = (const uint4*)s_lab8;
                unsigned myl4 = (unsigned)mylab * 0x01010101u;
                int nw16 = tid >> 4;
                for (int jw = 0; jw < nw16; ++jw) {
                    uint4 L = lab16[jw];
                    unsigned m0 = __vcmpeq4(L.x, myl4);
                    unsigned m1 = __vcmpeq4(L.y, myl4);
                    unsigned m2 = __vcmpeq4(L.z, myl4);
                    unsigned m3 = __vcmpeq4(L.w, myl4);
                    if ((m0 | m1 | m2 | m3) != 0u) {
                        unsigned mw[4] = { m0, m1, m2, m3 };
                        #pragma unroll
                        for (int w = 0; w < 4; ++w) {
                            unsigned m = mw[w];
                            while (m != 0u) {
                                int bit = __ffs(m) - 1;
                                m &= m - 1u;
                                if ((bit & 7) == 0) {
                                    int j = jw * 16 + w * 4 + (bit >> 3);
                                    if (iou_gt(s_box[j], mybox)) {
                                        s_row[tid][j >> 5] |= (1u << (j & 31));
                                        any = 1u;
                                    }
                                }
                            }
                        }
                    }
                }
                for (int j = nw16 * 16; j < tid; ++j) {
                    if (s_lab8[j] == (unsigned char)mylab && iou_gt(s_box[j], mybox)) {
                        s_row[tid][j >> 5] |= (1u << (j & 31));
                        any = 1u;
                    }
                }
            }
            s_flags[tid] = (unsigned char)(pred | (any << 1));
        }
        __syncthreads();

        // ---- greedy: single thread, 16 flags per LDS.128, kept mask in registers ----
        if (tid == 0) {
            unsigned K0=0,K1=0,K2=0,K3=0,K4=0,K5=0,K6=0,K7=0;
            int kc = kc0;
            int nk = 0;
            const uint4* f16 = (const uint4*)s_flags;
            for (int g = 0; g < CCAP / 16 && kc < MAXDET; ++g) {
                int c0 = g * 16;
                if (c0 >= cN) break;
                uint4 fv = f16[g];
                if ((fv.x | fv.y | fv.z | fv.w) == 0u && c0 + 16 <= cN && kc + 16 <= MAXDET) {
                    unsigned bits = 0xFFFFu << (c0 & 16);
                    switch (c0 >> 5) {
                        case 0: K0 |= bits; break; case 1: K1 |= bits; break;
                        case 2: K2 |= bits; break; case 3: K3 |= bits; break;
                        case 4: K4 |= bits; break; case 5: K5 |= bits; break;
                        case 6: K6 |= bits; break; default: K7 |= bits; break;
                    }
                    #pragma unroll
                    for (int t = 0; t < 16; ++t) s_kord[nk + t] = (unsigned char)(c0 + t);
                    nk += 16; kc += 16;
                    continue;
                }
                unsigned fwv[4] = { fv.x, fv.y, fv.z, fv.w };
                #pragma unroll
                for (int w = 0; w < 4; ++w) {
                    unsigned fw = fwv[w];
                    int cw = c0 + w * 4;
                    #pragma unroll
                    for (int t = 0; t < 4; ++t) {
                        int c = cw + t;
                        if (c >= cN || kc >= MAXDET) break;
                        unsigned fb = (fw >> (t * 8)) & 0xFFu;
                        bool alive;
                        if (fb == 0u) alive = true;
                        else if (fb & 1u) alive = false;
                        else {
                            const uint4* rp = (const uint4*)&s_row[c][0];
                            uint4 r0 = rp[0], r1 = rp[1];
                            alive = ((r0.x & K0) | (r0.y & K1) | (r0.z & K2) | (r0.w & K3) |
                                     (r1.x & K4) | (r1.y & K5) | (r1.z & K6) | (r1.w & K7)) == 0u;
                        }
                        if (alive) {
                            unsigned bit = 1u << (c & 31);
                            switch (c >> 5) {
                                case 0: K0 |= bit; break; case 1: K1 |= bit; break;
                                case 2: K2 |= bit; break; case 3: K3 |= bit; break;
                                case 4: K4 |= bit; break; case 5: K5 |= bit; break;
                                case 6: K6 |= bit; break; default: K7 |= bit; break;
                            }
                            s_kord[nk] = (unsigned char)c;
                            ++nk; ++kc;
                        }
                    }
                }
            }
            s_kc = kc;
            s_cnt = nk;
        }
        __syncthreads();

        {
            int nk = s_cnt;
            if (tid < nk) {
                int c = s_kord[tid];
                int slot = kc0 + tid;
                s_keptb[slot] = s_box[c];
                s_klab[slot]  = s_lab8[c];
                s_kepti[slot] = (int)(s_key[c] & 0xFFFFFFFFull);
            }
        }
        __syncthreads();
    }
    __syncthreads();

    // ---- outputs: boxes | scores | labels | valid ----
    int kc = s_kc;
    float* ob  = out;
    float* osc = out + (size_t)B * MAXDET * 4;
    float* olb = osc + (size_t)B * MAXDET;
    float* ovl = olb + (size_t)B * MAXDET;

    if (tid < MAXDET) {
        int r = tid;
        float4 bx = make_float4(0.f, 0.f, 0.f, 0.f);
        float scv = 0.f, lb = -1.f, vl = 0.f;
        if (r < kc) {
            int idx = s_kepti[r];
            bx = g_boxes[base + idx];
            scv = g_scores[base + idx];
            lb = (float)g_labels[base + idx];
            vl = 1.0f;
        }
        float* obp = ob + ((size_t)b * MAXDET + r) * 4;
        obp[0] = bx.x; obp[1] = bx.y; obp[2] = bx.z; obp[3] = bx.w;
        osc[(size_t)b * MAXDET + r] = scv;
        olb[(size_t)b * MAXDET + r] = lb;
        ovl[(size_t)b * MAXDET + r] = vl;
    }
}

// ---------------- launch ----------------
extern "C" void kernel_launch(void* const* d_in, const int* in_sizes, int n_in,
                              void* d_out, int out_size)
{
    int B = in_sizes[0] / 512000;
    if (B < 1) B = 1;
    if (B > MAXB) B = MAXB;

    const float *cls[3], *reg[3], *obj[3];
    bool grouped = (n_in >= 9) && (in_sizes[1] == B * 128000);
    if (grouped) {
        for (int i = 0; i < 3; ++i) {
            cls[i] = (const float*)d_in[i];
            reg[i] = (const float*)d_in[3 + i];
            obj[i] = (const float*)d_in[6 + i];
        }
    } else {
        for (int i = 0; i < 3; ++i) {
            cls[i] = (const float*)d_in[3 * i];
            reg[i] = (const float*)d_in[3 * i + 1];
            obj[i] = (const float*)d_in[3 * i + 2];
        }
    }

    dim3 gd((NANCH / 2 + 255) / 256, B);     // 2 anchors/thread -> 17x32 = 544 CTAs
    k_decode<<<gd, 256>>>(cls[0], reg[0], obj[0],
                          cls[1], reg[1], obj[1],
                          cls[2], reg[2], obj[2]);
    dim3 gs((NANCH / 4 + 255) / 256, B);     // select sweeps scores as float4
    k_select<<<gs, 256>>>();
    k_nms<<<B, 256>>>((float*)d_out, B);
}

// round 9
// speedup vs baseline: 1.3808x; 1.3808x over previous
#include <cuda_runtime.h>
#include <math.h>

#define NANCH   8400
#define MAXB    32
#define NCLS    80
#define MAXDET  100
#define NBKT    1024
#define CCAP    256      // chunk capacity (= NMS sort width = blockDim)
#define CAPSEL  280      // preselect target
#define LISTCAP 1024     // per-image candidate list capacity

// ---------------- device scratch (static zero-init; self-cleaning across graph replays) ----------------
__device__ float              g_scores[MAXB * NANCH];
__device__ float4             g_boxes [MAXB * NANCH];
__device__ int                g_labels[MAXB * NANCH];
__device__ int                g_maxabs[MAXB];
__device__ int                g_hist  [MAXB][NBKT];
__device__ unsigned long long g_cand  [MAXB][LISTCAP];
__device__ int                g_ccnt  [MAXB];

__device__ __forceinline__ float sigmoidf_(float x) {
    return 1.0f / (1.0f + expf(-x));
}

__device__ __forceinline__ int score_bucket(float scv) {
    int bkt = (int)(scv * 1024.0f);
    return bkt > NBKT - 1 ? NBKT - 1 : bkt;
}

__device__ __forceinline__ unsigned long long make_key(float scv, unsigned idx) {
    unsigned u = __float_as_uint(scv);
    u = ~(u ^ 0x80000000u);
    return ((unsigned long long)u << 32) | idx;
}

__device__ __forceinline__ float key_score(unsigned long long k) {
    unsigned u = (unsigned)(k >> 32);
    return __uint_as_float((~u) ^ 0x80000000u);
}

__device__ int compute_tcut(const int* hist, int lane) {
    int base = 1023 - 32 * lane;
    int s = 0;
    #pragma unroll 8
    for (int k = 0; k < 32; ++k) s += hist[base - k];
    int cum = s;
    #pragma unroll
    for (int o = 1; o < 32; o <<= 1) {
        int v = __shfl_up_sync(0xFFFFFFFFu, cum, o);
        if (lane >= o) cum += v;
    }
    int tcut = 0;
    unsigned ball = __ballot_sync(0xFFFFFFFFu, cum >= CAPSEL);
    if (ball) {
        int l0 = __ffs(ball) - 1;
        if (lane == l0) {
            int run = cum - s;
            int k = 0;
            for (; k < 32; ++k) {
                run += hist[base - k];
                if (run >= CAPSEL) break;
            }
            tcut = base - k;
        }
        tcut = __shfl_sync(0xFFFFFFFFu, tcut, l0);
    }
    return tcut;
}

// ---------------- decode: R7 float4 version (measured 32.7us) ----------------
__global__ void __launch_bounds__(256) k_decode(
    const float* __restrict__ cls0, const float* __restrict__ reg0, const float* __restrict__ obj0,
    const float* __restrict__ cls1, const float* __restrict__ reg1, const float* __restrict__ obj1,
    const float* __restrict__ cls2, const float* __restrict__ reg2, const float* __restrict__ obj2)
{
    __shared__ int s_h[NBKT];
    const int b   = blockIdx.y;
    const int tid = threadIdx.x;
    const int a   = (blockIdx.x * blockDim.x + tid) * 4;
    float m4 = 0.0f;

    ((int4*)s_h)[tid] = make_int4(0, 0, 0, 0);
    __syncthreads();

    if (a < NANCH) {
        const float *cls, *reg, *obj;
        int a0, w, hw; float s;
        if (a < 6400)      { cls = cls0; reg = reg0; obj = obj0; a0 = a;        w = 80; hw = 6400; s = 8.0f;  }
        else if (a < 8000) { cls = cls1; reg = reg1; obj = obj1; a0 = a - 6400; w = 40; hw = 1600; s = 16.0f; }
        else               { cls = cls2; reg = reg2; obj = obj2; a0 = a - 8000; w = 20; hw = 400;  s = 32.0f; }

        const int hw4 = hw >> 2;
        const int q   = a0 >> 2;

        const float4* c4 = (const float4*)(cls + (size_t)b * NCLS * hw) + q;
        float4 v = c4[0];
        float m0 = v.x, m1 = v.y, m2 = v.z, m3 = v.w;
        int   l0 = 0,   l1 = 0,   l2 = 0,   l3 = 0;
        #pragma unroll 4
        for (int c = 1; c < NCLS; ++c) {
            v = c4[(size_t)c * hw4];
            if (v.x > m0) { m0 = v.x; l0 = c; }
            if (v.y > m1) { m1 = v.y; l1 = c; }
            if (v.z > m2) { m2 = v.z; l2 = c; }
            if (v.w > m3) { m3 = v.w; l3 = c; }
        }

        float4 ov = *((const float4*)(obj + (size_t)b * hw) + q);
        const float* rb = reg + (size_t)b * 4 * hw;
        float4 r0 = *((const float4*)(rb)          + q);
        float4 r1 = *((const float4*)(rb +     hw) + q);
        float4 r2 = *((const float4*)(rb + 2 * hw) + q);
        float4 r3 = *((const float4*)(rb + 3 * hw) + q);

        float mm[4] = { m0, m1, m2, m3 };
        int   ll[4] = { l0, l1, l2, l3 };
        float oo[4] = { ov.x, ov.y, ov.z, ov.w };
        float rx[4] = { r0.x, r0.y, r0.z, r0.w };
        float ry[4] = { r1.x, r1.y, r1.z, r1.w };
        float rw[4] = { r2.x, r2.y, r2.z, r2.w };
        float rh[4] = { r3.x, r3.y, r3.z, r3.w };

        const size_t base = (size_t)b * NANCH + a;
        float sc[4];
        #pragma unroll
        for (int i = 0; i < 4; ++i) {
            sc[i] = __fmul_rn(sigmoidf_(mm[i]), sigmoidf_(oo[i]));
            int ai = a0 + i;
            float px = (float)(ai % w) * s;
            float py = (float)(ai / w) * s;
            float cx = __fadd_rn(__fmul_rn(rx[i], s), px);
            float cy = __fadd_rn(__fmul_rn(ry[i], s), py);
            float bw = __fmul_rn(expf(rw[i]), s);
            float bh = __fmul_rn(expf(rh[i]), s);
            float hx = __fmul_rn(bw, 0.5f);
            float hy = __fmul_rn(bh, 0.5f);
            float x1 = __fsub_rn(cx, hx), y1 = __fsub_rn(cy, hy);
            float x2 = __fadd_rn(cx, hx), y2 = __fadd_rn(cy, hy);
            g_boxes[base + i] = make_float4(x1, y1, x2, y2);
            m4 = fmaxf(m4, fmaxf(fmaxf(fabsf(x1), fabsf(y1)), fmaxf(fabsf(x2), fabsf(y2))));
            if (sc[i] >= 0.01f)
                atomicAdd(&s_h[score_bucket(sc[i])], 1);
        }
        *((float4*)(g_scores + base)) = make_float4(sc[0], sc[1], sc[2], sc[3]);
        *((int4*)(g_labels + base))   = make_int4(ll[0], ll[1], ll[2], ll[3]);
    }

    #pragma unroll
    for (int o = 16; o > 0; o >>= 1)
        m4 = fmaxf(m4, __shfl_xor_sync(0xFFFFFFFFu, m4, o));
    if ((threadIdx.x & 31) == 0 && m4 > 0.0f)
        atomicMax(&g_maxabs[b], __float_as_int(m4));

    __syncthreads();
    #pragma unroll
    for (int k = tid; k < NBKT; k += 256) {
        int hv = s_h[k];
        if (hv) atomicAdd(&g_hist[b][k], hv);
    }
}

// ---------------- select: compact top-(>=CAPSEL) candidates into per-image list ----------------
__global__ void __launch_bounds__(256) k_select()
{
    __shared__ int s_h[NBKT];
    __shared__ int s_tcut;
    const int b   = blockIdx.y;
    const int tid = threadIdx.x;

    ((int4*)s_h)[tid] = ((const int4*)&g_hist[b][0])[tid];
    __syncthreads();
    if (tid < 32) {
        int t = compute_tcut(s_h, tid);
        if (tid == 0) s_tcut = t;
    }
    __syncthreads();
    const int tcut = s_tcut;

    const int i4 = blockIdx.x * 256 + tid;
    if (i4 < NANCH / 4) {
        float4 s4 = *((const float4*)(g_scores + (size_t)b * NANCH) + i4);
        float sv[4] = { s4.x, s4.y, s4.z, s4.w };
        #pragma unroll
        for (int k = 0; k < 4; ++k) {
            float scv = sv[k];
            if (scv >= 0.01f && score_bucket(scv) >= tcut) {
                int slot = atomicAdd(&g_ccnt[b], 1);
                if (slot < LISTCAP)
                    g_cand[b][slot] = make_key(scv, (unsigned)(i4 * 4 + k));
            }
        }
    }
}

__device__ __forceinline__ unsigned long long shflx64(unsigned long long v, int j) {
    return __shfl_xor_sync(0xFFFFFFFFu, v, j);
}

// exact reference IoU>thr test on offset boxes
__device__ __forceinline__ bool iou_gt(float4 a, float4 bx) {
    float tlx = fmaxf(a.x, bx.x), tly = fmaxf(a.y, bx.y);
    float brx = fminf(a.z, bx.z), bry = fminf(a.w, bx.w);
    float ww = fmaxf(__fsub_rn(brx, tlx), 0.0f);
    float hh = fmaxf(__fsub_rn(bry, tly), 0.0f);
    float inter = __fmul_rn(ww, hh);
    float a1 = __fmul_rn(__fsub_rn(a.z, a.x), __fsub_rn(a.w, a.y));
    float a2 = __fmul_rn(__fsub_rn(bx.z, bx.x), __fsub_rn(bx.w, bx.y));
    float den = __fadd_rn(__fsub_rn(__fadd_rn(a1, a2), inter), 1e-6f);
    return __fdiv_rn(inter, den) > 0.65f;
}

// ---------------- NMS: per-class parallel greedy + rank selection ----------------
__global__ void __launch_bounds__(256) k_nms(float* __restrict__ out, int B)
{
    __shared__ __align__(16) int                s_hist[NBKT];
    __shared__ __align__(16) unsigned long long s_key[CCAP];
    __shared__ __align__(16) float4             s_box[CCAP];
    __shared__ __align__(16) unsigned           s_cmask[NCLS][8];  // per-class membership over sorted candidates
    __shared__ __align__(16) unsigned char      s_lab8[CCAP];
    __shared__ __align__(16) unsigned char      s_alive[CCAP];
    __shared__ unsigned           s_abits[8];
    __shared__ float4             s_keptb[MAXDET];      // global picks (across rounds)
    __shared__ unsigned char      s_klab[MAXDET];
    __shared__ int                s_kepti[MAXDET];
    __shared__ float              s_off;
    __shared__ int                s_cnt, s_kc, s_lo, s_hi, s_ptr, s_tcut, s_ccnt;

    const int b    = blockIdx.x;
    const int tid  = threadIdx.x;
    const int wid  = tid >> 5;
    const int lane = tid & 31;
    const size_t base = (size_t)b * NANCH;

    if (tid == 0) {
        s_off = __fadd_rn(__int_as_float(g_maxabs[b]), 1.0f);
        g_maxabs[b] = 0;
        s_ptr = -1;
        s_kc = 0;
        s_ccnt = g_ccnt[b];
        g_ccnt[b] = 0;
    }
    int4 h4;
    {
        int4* gh4 = (int4*)&g_hist[b][0];
        h4 = gh4[tid];
        ((int4*)s_hist)[tid] = h4;
        gh4[tid] = make_int4(0, 0, 0, 0);
    }
    __syncthreads();
    {
        int maxk = -1;
        if (h4.w) maxk = tid * 4 + 3;
        else if (h4.z) maxk = tid * 4 + 2;
        else if (h4.y) maxk = tid * 4 + 1;
        else if (h4.x) maxk = tid * 4;
        #pragma unroll
        for (int o = 16; o > 0; o >>= 1)
            maxk = max(maxk, __shfl_xor_sync(0xFFFFFFFFu, maxk, o));
        if ((tid & 31) == 0) atomicMax(&s_ptr, maxk);
        if (tid < 32) {
            int t = compute_tcut(s_hist, tid);
            if (tid == 0) s_tcut = t;
        }
    }
    __syncthreads();
    const float off = s_off;
    const int   tcut = s_tcut;
    const int   ccnt = s_ccnt;
    const bool  list_ok = (ccnt <= LISTCAP);

    for (;;) {
        if (s_kc >= MAXDET || s_ptr < 0) break;

        if (tid == 0) {
            int acc = 0;
            int hi = s_ptr, p = hi;
            while (p >= 0) {
                int h = s_hist[p];
                if (acc > 0 && acc + h > CCAP) break;
                acc += h; --p;
                if (acc >= CCAP) break;
            }
            s_lo = p + 1; s_hi = hi; s_ptr = p; s_cnt = 0;
        }
        __syncthreads();
        const int lo = s_lo, hi = s_hi;

        // ---- compact (list mode; exact full-sweep fallback) ----
        if (list_ok && lo >= tcut) {
            for (int t = tid; t < ccnt; t += 256) {
                unsigned long long key = g_cand[b][t];
                int bkt = score_bucket(key_score(key));
                if (bkt >= lo && bkt <= hi) {
                    int p = atomicAdd(&s_cnt, 1);
                    if (p < CCAP) s_key[p] = key;
                }
            }
        } else {
            for (int i4 = tid; i4 < NANCH / 4; i4 += 256) {
                float4 s4 = *((const float4*)(g_scores + base) + i4);
                float sv[4] = { s4.x, s4.y, s4.z, s4.w };
                #pragma unroll
                for (int k = 0; k < 4; ++k) {
                    float scv = sv[k];
                    if (scv >= 0.01f) {
                        int bkt = score_bucket(scv);
                        if (bkt >= lo && bkt <= hi) {
                            int p = atomicAdd(&s_cnt, 1);
                            if (p < CCAP) s_key[p] = make_key(scv, (unsigned)(i4 * 4 + k));
                        }
                    }
                }
            }
        }
        __syncthreads();
        int cN = s_cnt; if (cN > CCAP) cN = CCAP;
        if (tid >= cN) s_key[tid] = 0xFFFFFFFFFFFFFFFFull;

        // ---- bitonic sort 256 keys ascending (= score desc, idx asc) ----
        {
            unsigned long long v = s_key[tid];
            #pragma unroll
            for (int k = 2; k <= 32; k <<= 1) {
                bool up = ((tid & k) == 0);
                #pragma unroll
                for (int j = k >> 1; j > 0; j >>= 1) {
                    unsigned long long p = shflx64(v, j);
                    bool keepSmall = (((tid & j) == 0) == up);
                    if (keepSmall ? (p < v) : (p > v)) v = p;
                }
            }
            s_key[tid] = v;
            __syncthreads();
        }
        #pragma unroll
        for (int k = 64; k <= CCAP; k <<= 1) {
            for (int j = k >> 1; j >= 32; j >>= 1) {
                int i = tid, l = i ^ j;
                if (l > i) {
                    unsigned long long A = s_key[i], Bv = s_key[l];
                    bool up = ((i & k) == 0);
                    if ((A > Bv) == up) { s_key[i] = Bv; s_key[l] = A; }
                }
                __syncthreads();
            }
            {
                unsigned long long v = s_key[tid];
                bool up = ((tid & k) == 0);
                #pragma unroll
                for (int j = 16; j > 0; j >>= 1) {
                    unsigned long long p = shflx64(v, j);
                    bool keepSmall = (((tid & j) == 0) == up);
                    if (keepSmall ? (p < v) : (p > v)) v = p;
                }
                s_key[tid] = v;
                __syncthreads();
            }
        }

        // ---- gather boxes/labels; predead vs previous picks; build class masks ----
        const int kc0 = s_kc;
        {
            // zero class masks (80*8 = 640 words) + alive bytes
            if (tid < 128) {
                ((uint4*)&s_cmask[0][0])[tid];   // no-op read avoided; write below
            }
        }
        #pragma unroll
        for (int z = tid; z < NCLS * 8; z += 256) ((unsigned*)s_cmask)[z] = 0u;
        s_alive[tid] = 0;
        __syncthreads();

        {
            if (tid < cN) {
                int idx = (int)(s_key[tid] & 0xFFFFFFFFull);
                float4 mybox = g_boxes[base + idx];
                int mylab = g_labels[base + idx];
                float t = __fmul_rn((float)mylab, off);
                mybox.x = __fadd_rn(mybox.x, t);
                mybox.y = __fadd_rn(mybox.y, t);
                mybox.z = __fadd_rn(mybox.z, t);
                mybox.w = __fadd_rn(mybox.w, t);
                s_box[tid]  = mybox;
                s_lab8[tid] = (unsigned char)mylab;
                int pred = 0;
                for (int j2 = 0; j2 < kc0; ++j2)
                    if (s_klab[j2] == (unsigned char)mylab && iou_gt(s_keptb[j2], mybox)) { pred = 1; break; }
                if (!pred)
                    atomicOr(&s_cmask[mylab][tid >> 5], 1u << (tid & 31));
            }
        }
        __syncthreads();

        // ---- per-class greedy: 80 independent tiny serial NMS chains in parallel ----
        if (tid < NCLS) {
            unsigned char kl[CCAP];    // survivor indices of this class (local mem; touched ~k_c)
            int nkl = 0;
            #pragma unroll
            for (int w = 0; w < 8; ++w) {
                unsigned m = s_cmask[tid][w];
                while (m != 0u) {
                    int c = (w << 5) + (__ffs(m) - 1);
                    m &= m - 1u;
                    float4 cb = s_box[c];
                    bool dead = false;
                    for (int j = 0; j < nkl; ++j) {
                        if (iou_gt(s_box[kl[j]], cb)) { dead = true; break; }
                    }
                    if (!dead) {
                        s_alive[c] = 1;
                        kl[nkl++] = (unsigned char)c;
                    }
                }
            }
        }
        __syncthreads();

        // ---- selection: survivor rank via ballots; first (MAXDET-kc0) become picks ----
        {
            unsigned bal = __ballot_sync(0xFFFFFFFFu, s_alive[tid] != 0);
            if (lane == 0) s_abits[wid] = bal;
        }
        __syncthreads();
        {
            int pre = 0;
            #pragma unroll
            for (int w = 0; w < 8; ++w)
                pre += (w < wid) ? __popc(s_abits[w]) : 0;
            if (s_alive[tid]) {
                int rank = pre + __popc(s_abits[wid] & ((lane == 0) ? 0u : (0xFFFFFFFFu >> (32 - lane))));
                int slot = kc0 + rank;
                if (slot < MAXDET) {
                    s_keptb[slot] = s_box[tid];
                    s_klab[slot]  = s_lab8[tid];
                    s_kepti[slot] = (int)(s_key[tid] & 0xFFFFFFFFull);
                }
            }
            if (tid == 0) {
                int tot = 0;
                #pragma unroll
                for (int w = 0; w < 8; ++w) tot += __popc(s_abits[w]);
                int kc = kc0 + tot;
                s_kc = kc > MAXDET ? MAXDET : kc;
            }
        }
        __syncthreads();
    }
    __syncthreads();

    // ---- outputs: boxes | scores | labels | valid ----
    int kc = s_kc;
    float* ob  = out;
    float* osc = out + (size_t)B * MAXDET * 4;
    float* olb = osc + (size_t)B * MAXDET;
    float* ovl = olb + (size_t)B * MAXDET;

    if (tid < MAXDET) {
        int r = tid;
        float4 bx = make_float4(0.f, 0.f, 0.f, 0.f);
        float scv = 0.f, lb = -1.f, vl = 0.f;
        if (r < kc) {
            int idx = s_kepti[r];
            bx = g_boxes[base + idx];
            scv = g_scores[base + idx];
            lb = (float)g_labels[base + idx];
            vl = 1.0f;
        }
        float* obp = ob + ((size_t)b * MAXDET + r) * 4;
        obp[0] = bx.x; obp[1] = bx.y; obp[2] = bx.z; obp[3] = bx.w;
        osc[(size_t)b * MAXDET + r] = scv;
        olb[(size_t)b * MAXDET + r] = lb;
        ovl[(size_t)b * MAXDET + r] = vl;
    }
}

// ---------------- launch ----------------
extern "C" void kernel_launch(void* const* d_in, const int* in_sizes, int n_in,
                              void* d_out, int out_size)
{
    int B = in_sizes[0] / 512000;
    if (B < 1) B = 1;
    if (B > MAXB) B = MAXB;

    const float *cls[3], *reg[3], *obj[3];
    bool grouped = (n_in >= 9) && (in_sizes[1] == B * 128000);
    if (grouped) {
        for (int i = 0; i < 3; ++i) {
            cls[i] = (const float*)d_in[i];
            reg[i] = (const float*)d_in[3 + i];
            obj[i] = (const float*)d_in[6 + i];
        }
    } else {
        for (int i = 0; i < 3; ++i) {
            cls[i] = (const float*)d_in[3 * i];
            reg[i] = (const float*)d_in[3 * i + 1];
            obj[i] = (const float*)d_in[3 * i + 2];
        }
    }

    dim3 g1((NANCH / 4 + 255) / 256, B);
    k_decode<<<g1, 256>>>(cls[0], reg[0], obj[0],
                          cls[1], reg[1], obj[1],
                          cls[2], reg[2], obj[2]);
    k_select<<<g1, 256>>>();
    k_nms<<<B, 256>>>((float*)d_out, B);
}

// round 11
// speedup vs baseline: 1.4382x; 1.0415x over previous
#include <cuda_runtime.h>
#include <math.h>

#define NANCH   8400
#define MAXB    32
#define NCLS    80
#define MAXDET  100
#define NBKT    1024
#define CCAP    256      // chunk capacity (= NMS sort width = blockDim)
#define CAPSEL  280      // preselect target
#define LISTCAP 1024     // per-image candidate list capacity

// ---------------- device scratch (static zero-init; self-cleaning across graph replays) ----------------
__device__ float              g_scores[MAXB * NANCH];
__device__ float4             g_boxes [MAXB * NANCH];
__device__ int                g_labels[MAXB * NANCH];
__device__ int                g_maxabs[MAXB];
__device__ int                g_hist  [MAXB][NBKT];
__device__ unsigned long long g_cand  [MAXB][LISTCAP];
__device__ int                g_ccnt  [MAXB];

__device__ __forceinline__ float sigmoidf_(float x) {
    return 1.0f / (1.0f + expf(-x));
}

__device__ __forceinline__ int score_bucket(float scv) {
    int bkt = (int)(scv * 1024.0f);
    return bkt > NBKT - 1 ? NBKT - 1 : bkt;
}

__device__ __forceinline__ unsigned long long make_key(float scv, unsigned idx) {
    unsigned u = __float_as_uint(scv);
    u = ~(u ^ 0x80000000u);
    return ((unsigned long long)u << 32) | idx;
}

__device__ __forceinline__ float key_score(unsigned long long k) {
    unsigned u = (unsigned)(k >> 32);
    return __uint_as_float((~u) ^ 0x80000000u);
}

__device__ int compute_tcut(const int* hist, int lane) {
    int base = 1023 - 32 * lane;
    int s = 0;
    #pragma unroll 8
    for (int k = 0; k < 32; ++k) s += hist[base - k];
    int cum = s;
    #pragma unroll
    for (int o = 1; o < 32; o <<= 1) {
        int v = __shfl_up_sync(0xFFFFFFFFu, cum, o);
        if (lane >= o) cum += v;
    }
    int tcut = 0;
    unsigned ball = __ballot_sync(0xFFFFFFFFu, cum >= CAPSEL);
    if (ball) {
        int l0 = __ffs(ball) - 1;
        if (lane == l0) {
            int run = cum - s;
            int k = 0;
            for (; k < 32; ++k) {
                run += hist[base - k];
                if (run >= CAPSEL) break;
            }
            tcut = base - k;
        }
        tcut = __shfl_sync(0xFFFFFFFFu, tcut, l0);
    }
    return tcut;
}

// ---------------- decode: split-class thread pairs, float4 loads, 2 anchors/thread output ----------------
// Pair (2 threads) handles 4 anchors: even thread scans classes 0..39, odd 40..79 (both LDG.128),
// merge via shfl_xor(1) executed CONVERGENTLY (tail threads clamped, stores guarded).
__global__ void __launch_bounds__(256) k_decode(
    const float* __restrict__ cls0, const float* __restrict__ reg0, const float* __restrict__ obj0,
    const float* __restrict__ cls1, const float* __restrict__ reg1, const float* __restrict__ obj1,
    const float* __restrict__ cls2, const float* __restrict__ reg2, const float* __restrict__ obj2)
{
    __shared__ int s_h[NBKT];
    const int b    = blockIdx.y;
    const int tid  = threadIdx.x;
    const int half = tid & 1;
    const int g    = blockIdx.x * 128 + (tid >> 1);   // anchor group (4 anchors)
    const bool act = (g < NANCH / 4);
    const int gc   = act ? g : (NANCH / 4 - 1);       // clamped: tail threads compute redundantly
    const int a    = gc * 4;
    float m4 = 0.0f;

    ((int4*)s_h)[tid] = make_int4(0, 0, 0, 0);
    __syncthreads();

    const float *cls, *reg, *obj;
    int a0, w, hw; float s;
    if (a < 6400)      { cls = cls0; reg = reg0; obj = obj0; a0 = a;        w = 80; hw = 6400; s = 8.0f;  }
    else if (a < 8000) { cls = cls1; reg = reg1; obj = obj1; a0 = a - 6400; w = 40; hw = 1600; s = 16.0f; }
    else               { cls = cls2; reg = reg2; obj = obj2; a0 = a - 8000; w = 20; hw = 400;  s = 32.0f; }

    const int hw4 = hw >> 2;
    const int q   = a0 >> 2;
    const int lb0 = half * 40;                         // this thread's class base

    // ---- partial argmax over 40 classes (float4 = 4 anchors wide) ----
    const float4* c4 = (const float4*)(cls + (size_t)b * NCLS * hw) + (size_t)lb0 * hw4 + q;
    float4 v = c4[0];
    float m0 = v.x, m1 = v.y, m2 = v.z, m3 = v.w;
    int   l0 = lb0, l1 = lb0, l2 = lb0, l3 = lb0;
    #pragma unroll 4
    for (int c = 1; c < 40; ++c) {
        v = c4[(size_t)c * hw4];
        if (v.x > m0) { m0 = v.x; l0 = lb0 + c; }
        if (v.y > m1) { m1 = v.y; l1 = lb0 + c; }
        if (v.z > m2) { m2 = v.z; l2 = lb0 + c; }
        if (v.w > m3) { m3 = v.w; l3 = lb0 + c; }
    }

    // ---- merge halves (convergent; low half wins ties = first-index argmax) ----
    float mm[4] = { m0, m1, m2, m3 };
    int   ll[4] = { l0, l1, l2, l3 };
    #pragma unroll
    for (int i = 0; i < 4; ++i) {
        float om = __shfl_xor_sync(0xFFFFFFFFu, mm[i], 1);
        int   ol = __shfl_xor_sync(0xFFFFFFFFu, ll[i], 1);
        float lom = half ? om : mm[i];
        int   lol = half ? ol : ll[i];
        float him = half ? mm[i] : om;
        int   hil = half ? ll[i] : ol;
        if (him > lom) { mm[i] = him; ll[i] = hil; }
        else           { mm[i] = lom; ll[i] = lol; }
    }

    // ---- reg/obj loads (both halves load; L2-hit dup is cheap) ----
    float4 ov = *((const float4*)(obj + (size_t)b * hw) + q);
    const float* rb = reg + (size_t)b * 4 * hw;
    float4 r0 = *((const float4*)(rb)          + q);
    float4 r1 = *((const float4*)(rb +     hw) + q);
    float4 r2 = *((const float4*)(rb + 2 * hw) + q);
    float4 r3 = *((const float4*)(rb + 3 * hw) + q);

    float oo[4] = { ov.x, ov.y, ov.z, ov.w };
    float rx[4] = { r0.x, r0.y, r0.z, r0.w };
    float ry[4] = { r1.x, r1.y, r1.z, r1.w };
    float rw[4] = { r2.x, r2.y, r2.z, r2.w };
    float rh[4] = { r3.x, r3.y, r3.z, r3.w };

    // ---- decode + store my 2 anchors (half*2, half*2+1); stores guarded by act ----
    const int i0 = half * 2;
    const size_t mybase = (size_t)b * NANCH + a + i0;
    float sc[2];
    int   lo2[2];
    #pragma unroll
    for (int k = 0; k < 2; ++k) {
        int i = i0 + k;
        sc[k]  = __fmul_rn(sigmoidf_(mm[i]), sigmoidf_(oo[i]));
        lo2[k] = ll[i];
        int ai = a0 + i;
        float px = (float)(ai % w) * s;
        float py = (float)(ai / w) * s;
        float cx = __fadd_rn(__fmul_rn(rx[i], s), px);
        float cy = __fadd_rn(__fmul_rn(ry[i], s), py);
        float bw = __fmul_rn(expf(rw[i]), s);
        float bh = __fmul_rn(expf(rh[i]), s);
        float hx = __fmul_rn(bw, 0.5f);
        float hy = __fmul_rn(bh, 0.5f);
        float x1 = __fsub_rn(cx, hx), y1 = __fsub_rn(cy, hy);
        float x2 = __fadd_rn(cx, hx), y2 = __fadd_rn(cy, hy);
        if (act) {
            g_boxes[mybase + k] = make_float4(x1, y1, x2, y2);
            m4 = fmaxf(m4, fmaxf(fmaxf(fabsf(x1), fabsf(y1)), fmaxf(fabsf(x2), fabsf(y2))));
            if (sc[k] >= 0.01f)
                atomicAdd(&s_h[score_bucket(sc[k])], 1);
        }
    }
    if (act) {
        *((float2*)(g_scores + mybase)) = make_float2(sc[0], sc[1]);
        *((int2*)(g_labels + mybase))   = make_int2(lo2[0], lo2[1]);
    }

    #pragma unroll
    for (int o = 16; o > 0; o >>= 1)
        m4 = fmaxf(m4, __shfl_xor_sync(0xFFFFFFFFu, m4, o));
    if ((threadIdx.x & 31) == 0 && m4 > 0.0f)
        atomicMax(&g_maxabs[b], __float_as_int(m4));

    __syncthreads();
    #pragma unroll
    for (int k = tid; k < NBKT; k += 256) {
        int hv = s_h[k];
        if (hv) atomicAdd(&g_hist[b][k], hv);
    }
}

// ---------------- select: compact top-(>=CAPSEL) candidates into per-image list ----------------
__global__ void __launch_bounds__(256) k_select()
{
    __shared__ int s_h[NBKT];
    __shared__ int s_tcut;
    const int b   = blockIdx.y;
    const int tid = threadIdx.x;

    ((int4*)s_h)[tid] = ((const int4*)&g_hist[b][0])[tid];
    __syncthreads();
    if (tid < 32) {
        int t = compute_tcut(s_h, tid);
        if (tid == 0) s_tcut = t;
    }
    __syncthreads();
    const int tcut = s_tcut;

    const int i4 = blockIdx.x * 256 + tid;
    if (i4 < NANCH / 4) {
        float4 s4 = *((const float4*)(g_scores + (size_t)b * NANCH) + i4);
        float sv[4] = { s4.x, s4.y, s4.z, s4.w };
        #pragma unroll
        for (int k = 0; k < 4; ++k) {
            float scv = sv[k];
            if (scv >= 0.01f && score_bucket(scv) >= tcut) {
                int slot = atomicAdd(&g_ccnt[b], 1);
                if (slot < LISTCAP)
                    g_cand[b][slot] = make_key(scv, (unsigned)(i4 * 4 + k));
            }
        }
    }
}

__device__ __forceinline__ unsigned long long shflx64(unsigned long long v, int j) {
    return __shfl_xor_sync(0xFFFFFFFFu, v, j);
}

// exact reference IoU>thr test on offset boxes
__device__ __forceinline__ bool iou_gt(float4 a, float4 bx) {
    float tlx = fmaxf(a.x, bx.x), tly = fmaxf(a.y, bx.y);
    float brx = fminf(a.z, bx.z), bry = fminf(a.w, bx.w);
    float ww = fmaxf(__fsub_rn(brx, tlx), 0.0f);
    float hh = fmaxf(__fsub_rn(bry, tly), 0.0f);
    float inter = __fmul_rn(ww, hh);
    float a1 = __fmul_rn(__fsub_rn(a.z, a.x), __fsub_rn(a.w, a.y));
    float a2 = __fmul_rn(__fsub_rn(bx.z, bx.x), __fsub_rn(bx.w, bx.y));
    float den = __fadd_rn(__fsub_rn(__fadd_rn(a1, a2), inter), 1e-6f);
    return __fdiv_rn(inter, den) > 0.65f;
}

// ---------------- NMS: per-class parallel greedy + rank selection ----------------
__global__ void __launch_bounds__(256) k_nms(float* __restrict__ out, int B)
{
    __shared__ __align__(16) int                s_hist[NBKT];
    __shared__ __align__(16) unsigned long long s_key[CCAP];
    __shared__ __align__(16) float4             s_box[CCAP];
    __shared__ __align__(16) unsigned           s_cmask[NCLS][8];
    __shared__ __align__(16) unsigned char      s_lab8[CCAP];
    __shared__ __align__(16) unsigned char      s_alive[CCAP];
    __shared__ unsigned           s_abits[8];
    __shared__ float4             s_keptb[MAXDET];
    __shared__ unsigned char      s_klab[MAXDET];
    __shared__ int                s_kepti[MAXDET];
    __shared__ float              s_off;
    __shared__ int                s_cnt, s_kc, s_lo, s_hi, s_ptr, s_tcut, s_ccnt;

    const int b    = blockIdx.x;
    const int tid  = threadIdx.x;
    const int wid  = tid >> 5;
    const int lane = tid & 31;
    const size_t base = (size_t)b * NANCH;

    if (tid == 0) {
        s_off = __fadd_rn(__int_as_float(g_maxabs[b]), 1.0f);
        g_maxabs[b] = 0;
        s_ptr = -1;
        s_kc = 0;
        s_ccnt = g_ccnt[b];
        g_ccnt[b] = 0;
    }
    int4 h4;
    {
        int4* gh4 = (int4*)&g_hist[b][0];
        h4 = gh4[tid];
        ((int4*)s_hist)[tid] = h4;
        gh4[tid] = make_int4(0, 0, 0, 0);
    }
    __syncthreads();
    {
        int maxk = -1;
        if (h4.w) maxk = tid * 4 + 3;
        else if (h4.z) maxk = tid * 4 + 2;
        else if (h4.y) maxk = tid * 4 + 1;
        else if (h4.x) maxk = tid * 4;
        #pragma unroll
        for (int o = 16; o > 0; o >>= 1)
            maxk = max(maxk, __shfl_xor_sync(0xFFFFFFFFu, maxk, o));
        if ((tid & 31) == 0) atomicMax(&s_ptr, maxk);
        if (tid < 32) {
            int t = compute_tcut(s_hist, tid);
            if (tid == 0) s_tcut = t;
        }
    }
    __syncthreads();
    const float off = s_off;
    const int   tcut = s_tcut;
    const int   ccnt = s_ccnt;
    const bool  list_ok = (ccnt <= LISTCAP);

    for (;;) {
        if (s_kc >= MAXDET || s_ptr < 0) break;

        if (tid == 0) {
            int acc = 0;
            int hi = s_ptr, p = hi;
            while (p >= 0) {
                int h = s_hist[p];
                if (acc > 0 && acc + h > CCAP) break;
                acc += h; --p;
                if (acc >= CCAP) break;
            }
            s_lo = p + 1; s_hi = hi; s_ptr = p; s_cnt = 0;
        }
        __syncthreads();
        const int lo = s_lo, hi = s_hi;

        // ---- compact (list mode; exact full-sweep fallback) ----
        if (list_ok && lo >= tcut) {
            for (int t = tid; t < ccnt; t += 256) {
                unsigned long long key = g_cand[b][t];
                int bkt = score_bucket(key_score(key));
                if (bkt >= lo && bkt <= hi) {
                    int p = atomicAdd(&s_cnt, 1);
                    if (p < CCAP) s_key[p] = key;
                }
            }
        } else {
            for (int i4 = tid; i4 < NANCH / 4; i4 += 256) {
                float4 s4 = *((const float4*)(g_scores + base) + i4);
                float sv[4] = { s4.x, s4.y, s4.z, s4.w };
                #pragma unroll
                for (int k = 0; k < 4; ++k) {
                    float scv = sv[k];
                    if (scv >= 0.01f) {
                        int bkt = score_bucket(scv);
                        if (bkt >= lo && bkt <= hi) {
                            int p = atomicAdd(&s_cnt, 1);
                            if (p < CCAP) s_key[p] = make_key(scv, (unsigned)(i4 * 4 + k));
                        }
                    }
                }
            }
        }
        __syncthreads();
        int cN = s_cnt; if (cN > CCAP) cN = CCAP;
        if (tid >= cN) s_key[tid] = 0xFFFFFFFFFFFFFFFFull;

        // ---- bitonic sort 256 keys ascending (= score desc, idx asc) ----
        {
            unsigned long long v = s_key[tid];
            #pragma unroll
            for (int k = 2; k <= 32; k <<= 1) {
                bool up = ((tid & k) == 0);
                #pragma unroll
                for (int j = k >> 1; j > 0; j >>= 1) {
                    unsigned long long p = shflx64(v, j);
                    bool keepSmall = (((tid & j) == 0) == up);
                    if (keepSmall ? (p < v) : (p > v)) v = p;
                }
            }
            s_key[tid] = v;
            __syncthreads();
        }
        #pragma unroll
        for (int k = 64; k <= CCAP; k <<= 1) {
            for (int j = k >> 1; j >= 32; j >>= 1) {
                int i = tid, l = i ^ j;
                if (l > i) {
                    unsigned long long A = s_key[i], Bv = s_key[l];
                    bool up = ((i & k) == 0);
                    if ((A > Bv) == up) { s_key[i] = Bv; s_key[l] = A; }
                }
                __syncthreads();
            }
            {
                unsigned long long v = s_key[tid];
                bool up = ((tid & k) == 0);
                #pragma unroll
                for (int j = 16; j > 0; j >>= 1) {
                    unsigned long long p = shflx64(v, j);
                    bool keepSmall = (((tid & j) == 0) == up);
                    if (keepSmall ? (p < v) : (p > v)) v = p;
                }
                s_key[tid] = v;
                __syncthreads();
            }
        }

        // ---- gather boxes/labels; predead vs previous picks; build class masks ----
        const int kc0 = s_kc;
        #pragma unroll
        for (int z = tid; z < NCLS * 8; z += 256) ((unsigned*)s_cmask)[z] = 0u;
        s_alive[tid] = 0;
        __syncthreads();

        if (tid < cN) {
            int idx = (int)(s_key[tid] & 0xFFFFFFFFull);
            float4 mybox = g_boxes[base + idx];
            int mylab = g_labels[base + idx];
            float t = __fmul_rn((float)mylab, off);
            mybox.x = __fadd_rn(mybox.x, t);
            mybox.y = __fadd_rn(mybox.y, t);
            mybox.z = __fadd_rn(mybox.z, t);
            mybox.w = __fadd_rn(mybox.w, t);
            s_box[tid]  = mybox;
            s_lab8[tid] = (unsigned char)mylab;
            int pred = 0;
            for (int j2 = 0; j2 < kc0; ++j2)
                if (s_klab[j2] == (unsigned char)mylab && iou_gt(s_keptb[j2], mybox)) { pred = 1; break; }
            if (!pred)
                atomicOr(&s_cmask[mylab][tid >> 5], 1u << (tid & 31));
        }
        __syncthreads();

        // ---- per-class greedy: 80 independent tiny serial NMS chains in parallel ----
        if (tid < NCLS) {
            unsigned char kl[CCAP];
            int nkl = 0;
            #pragma unroll
            for (int w = 0; w < 8; ++w) {
                unsigned m = s_cmask[tid][w];
                while (m != 0u) {
                    int c = (w << 5) + (__ffs(m) - 1);
                    m &= m - 1u;
                    float4 cb = s_box[c];
                    bool dead = false;
                    for (int j = 0; j < nkl; ++j) {
                        if (iou_gt(s_box[kl[j]], cb)) { dead = true; break; }
                    }
                    if (!dead) {
                        s_alive[c] = 1;
                        kl[nkl++] = (unsigned char)c;
                    }
                }
            }
        }
        __syncthreads();

        // ---- selection: survivor rank via ballots; first (MAXDET-kc0) become picks ----
        {
            unsigned bal = __ballot_sync(0xFFFFFFFFu, s_alive[tid] != 0);
            if (lane == 0) s_abits[wid] = bal;
        }
        __syncthreads();
        {
            int pre = 0;
            #pragma unroll
            for (int w = 0; w < 8; ++w)
                pre += (w < wid) ? __popc(s_abits[w]) : 0;
            if (s_alive[tid]) {
                int rank = pre + __popc(s_abits[wid] & ((lane == 0) ? 0u : (0xFFFFFFFFu >> (32 - lane))));
                int slot = kc0 + rank;
                if (slot < MAXDET) {
                    s_keptb[slot] = s_box[tid];
                    s_klab[slot]  = s_lab8[tid];
                    s_kepti[slot] = (int)(s_key[tid] & 0xFFFFFFFFull);
                }
            }
            if (tid == 0) {
                int tot = 0;
                #pragma unroll
                for (int w = 0; w < 8; ++w) tot += __popc(s_abits[w]);
                int kc = kc0 + tot;
                s_kc = kc > MAXDET ? MAXDET : kc;
            }
        }
        __syncthreads();
    }
    __syncthreads();

    // ---- outputs: boxes | scores | labels | valid ----
    int kc = s_kc;
    float* ob  = out;
    float* osc = out + (size_t)B * MAXDET * 4;
    float* olb = osc + (size_t)B * MAXDET;
    float* ovl = olb + (size_t)B * MAXDET;

    if (tid < MAXDET) {
        int r = tid;
        float4 bx = make_float4(0.f, 0.f, 0.f, 0.f);
        float scv = 0.f, lb = -1.f, vl = 0.f;
        if (r < kc) {
            int idx = s_kepti[r];
            bx = g_boxes[base + idx];
            scv = g_scores[base + idx];
            lb = (float)g_labels[base + idx];
            vl = 1.0f;
        }
        float* obp = ob + ((size_t)b * MAXDET + r) * 4;
        obp[0] = bx.x; obp[1] = bx.y; obp[2] = bx.z; obp[3] = bx.w;
        osc[(size_t)b * MAXDET + r] = scv;
        olb[(size_t)b * MAXDET + r] = lb;
        ovl[(size_t)b * MAXDET + r] = vl;
    }
}

// ---------------- launch ----------------
extern "C" void kernel_launch(void* const* d_in, const int* in_sizes, int n_in,
                              void* d_out, int out_size)
{
    int B = in_sizes[0] / 512000;
    if (B < 1) B = 1;
    if (B > MAXB) B = MAXB;

    const float *cls[3], *reg[3], *obj[3];
    bool grouped = (n_in >= 9) && (in_sizes[1] == B * 128000);
    if (grouped) {
        for (int i = 0; i < 3; ++i) {
            cls[i] = (const float*)d_in[i];
            reg[i] = (const float*)d_in[3 + i];
            obj[i] = (const float*)d_in[6 + i];
        }
    } else {
        for (int i = 0; i < 3; ++i) {
            cls[i] = (const float*)d_in[3 * i];
            reg[i] = (const float*)d_in[3 * i + 1];
            obj[i] = (const float*)d_in[3 * i + 2];
        }
    }

    dim3 gd((2100 + 127) / 128, B);          // pair-per-group: 17x32 = 544 CTAs, 256 thr
    k_decode<<<gd, 256>>>(cls[0], reg[0], obj[0],
                          cls[1], reg[1], obj[1],
                          cls[2], reg[2], obj[2]);
    dim3 gs((NANCH / 4 + 255) / 256, B);
    k_select<<<gs, 256>>>();
    k_nms<<<B, 256>>>((float*)d_out, B);
}